// round 13
// baseline (speedup 1.0000x reference)
#include <cuda_runtime.h>
#include <cuda_bf16.h>
#include <cstdint>

// ============================================================================
// EdgeAggregatorGATED round 13: fragment-exchange drains.
// R12 tensor-core structure kept. After each 8-col MMA block, shfl.xor(1)
// re-maps fragments to thread-owns-(1 row x 4 consecutive cols):
//   edge: RED.v2 -> RED.v4 (lane-ops halved), float4 gathers, gathers for
//         block p+1 prefetched during MMA of block p (row ptr loop-invariant)
//   node: STG.64x2 -> STG.128, float4 bias loads.
// ============================================================================

#define MAXN 51200
__device__ float g_kx[MAXN * 64];
__device__ float g_qx[MAXN * 64];
__device__ float g_vx[MAXN * 64];
__device__ uint4 g_Bpack[1024];    // edge B image, 16KB
__device__ uint4 g_BpackN[4096];   // node B image, 64KB (two 32KB halves)

__device__ __forceinline__ float fast_sigmoid(float s) {
    return __fdividef(1.0f, 1.0f + __expf(-s));
}
__device__ __forceinline__ unsigned smem_u32(const void* p) {
    return (unsigned)__cvta_generic_to_shared(p);
}
__device__ __forceinline__ uint32_t bf2(float a, float b) {
    uint32_t r; asm("cvt.rn.bf16x2.f32 %0, %1, %2;" : "=r"(r) : "f"(b), "f"(a));
    return r;
}
__device__ __forceinline__ float2 bf2_back(uint32_t h) {
    return make_float2(__uint_as_float(h << 16), __uint_as_float(h & 0xffff0000u));
}
__device__ __forceinline__ void split2(float a, float b, uint32_t& hi, uint32_t& lo) {
    hi = bf2(a, b);
    float2 hb = bf2_back(hi);
    lo = bf2(a - hb.x, b - hb.y);
}
__device__ __forceinline__ void mma_bf16(float c[4], const uint32_t a[4],
                                         uint32_t b0, uint32_t b1) {
    asm volatile(
        "mma.sync.aligned.m16n8k16.row.col.f32.bf16.bf16.f32 "
        "{%0,%1,%2,%3}, {%4,%5,%6,%7}, {%8,%9}, {%0,%1,%2,%3};"
        : "+f"(c[0]), "+f"(c[1]), "+f"(c[2]), "+f"(c[3])
        : "r"(a[0]), "r"(a[1]), "r"(a[2]), "r"(a[3]), "r"(b0), "r"(b1));
}

// Exchange fragment c[4] (2 rows x 2 cols) across lane pair (xor 1) into
// r[4] = 1 row x 4 consecutive cols. Even lane keeps its row (g), odd keeps g+8.
__device__ __forceinline__ void frag_exchange(const float c[4], float r[4], bool odd) {
    float sA = odd ? c[0] : c[2];
    float sB = odd ? c[1] : c[3];
    float rA = __shfl_xor_sync(0xffffffffu, sA, 1);
    float rB = __shfl_xor_sync(0xffffffffu, sB, 1);
    if (!odd) { r[0] = c[0]; r[1] = c[1]; r[2] = rA; r[3] = rB; }
    else      { r[0] = rA;   r[1] = rB;   r[2] = c[2]; r[3] = c[3]; }
}

// ----------------------------------------------------------------------------
// bpack (3 blocks x 256): block 0 = edge B [128n x 32k]; blocks 1,2 = node B
// [256n x 64k] (n: kx | qx | vx | skip). Fragment layout per R12.
// ----------------------------------------------------------------------------
__global__ void bpack_kernel(const float* __restrict__ Wk,
                             const float* __restrict__ Wq,
                             const float* __restrict__ Wv,
                             const float* __restrict__ Wskip)
{
    int t = threadIdx.x;
    if (blockIdx.x == 0) {
        #pragma unroll
        for (int i = 0; i < 4; ++i) {
            int s = t * 4 + i;
            int nt = s >> 6;
            int kt = (s >> 5) & 1;
            int lane = s & 31;
            int n = nt * 8 + (lane >> 2);
            int k0 = kt * 16 + 2 * (lane & 3);
            float f[4];
            #pragma unroll
            for (int j = 0; j < 4; ++j) {
                int k = k0 + (j >> 1) * 8 + (j & 1);
                f[j] = (n < 64) ? (Wk[(64 + k) * 64 + n] + Wq[(64 + k) * 64 + n])
                                : Wv[(64 + k) * 64 + (n - 64)];
            }
            uint32_t b0h, b0l, b1h, b1l;
            split2(f[0], f[1], b0h, b0l);
            split2(f[2], f[3], b1h, b1l);
            g_Bpack[s] = make_uint4(b0h, b1h, b0l, b1l);
        }
    } else {
        int base = (blockIdx.x - 1) * 2048;
        #pragma unroll
        for (int i = 0; i < 8; ++i) {
            int s = base + t * 8 + i;
            int nt = s >> 7;
            int kt = (s >> 5) & 3;
            int lane = s & 31;
            int n = nt * 8 + (lane >> 2);
            int k0 = kt * 16 + 2 * (lane & 3);
            const float* W = (n < 64) ? Wk : (n < 128) ? Wq : (n < 192) ? Wv : Wskip;
            int nc = n & 63;
            float f[4];
            #pragma unroll
            for (int j = 0; j < 4; ++j) {
                int k = k0 + (j >> 1) * 8 + (j & 1);
                f[j] = W[k * 64 + nc];
            }
            uint32_t b0h, b0l, b1h, b1l;
            split2(f[0], f[1], b0h, b0l);
            split2(f[2], f[3], b1h, b1l);
            g_BpackN[s] = make_uint4(b0h, b1h, b0l, b1l);
        }
    }
}

// ----------------------------------------------------------------------------
// Node kernel v3: tile 128 nodes x 128 cols, blockIdx.y = col half.
// Drain via frag_exchange -> STG.128 with float4 folded biases.
// ----------------------------------------------------------------------------
__global__ __launch_bounds__(256, 2) void node_kernel(
    const float* __restrict__ x,
    const float* __restrict__ bk, const float* __restrict__ bq,
    const float* __restrict__ bv, const float* __restrict__ bias,
    float* __restrict__ out, int N)
{
    __shared__ uint4 sB[2048];   // 32KB

    const int tid  = threadIdx.x;
    const int w    = tid >> 5;
    const int lane = tid & 31;
    const int g    = lane >> 2;
    const int tig  = lane & 3;
    const int half = blockIdx.y;

    {
        unsigned sb = smem_u32(sB);
        const uint4* src = g_BpackN + half * 2048;
        #pragma unroll
        for (int i = 0; i < 8; ++i) {
            int idx = tid * 8 + i;
            asm volatile("cp.async.cg.shared.global [%0], [%1], 16;"
                         :: "r"(sb + idx * 16), "l"(src + idx));
        }
        asm volatile("cp.async.commit_group;");
    }

    const int nbase = blockIdx.x * 128;
    int n0 = nbase + w * 16 + g;
    int n1 = n0 + 8;
    const bool v0 = (n0 < N), v1 = (n1 < N);
    const int n0c = v0 ? n0 : N - 1;
    const int n1c = v1 ? n1 : N - 1;

    uint32_t ah[4][4], al[4][4];
    #pragma unroll
    for (int kt = 0; kt < 4; ++kt) {
        const int k0 = kt * 16 + 2 * tig;
        float2 p0 = *(const float2*)(x + (size_t)n0c * 64 + k0);
        float2 p1 = *(const float2*)(x + (size_t)n1c * 64 + k0);
        float2 p2 = *(const float2*)(x + (size_t)n0c * 64 + k0 + 8);
        float2 p3 = *(const float2*)(x + (size_t)n1c * 64 + k0 + 8);
        split2(p0.x, p0.y, ah[kt][0], al[kt][0]);
        split2(p1.x, p1.y, ah[kt][1], al[kt][1]);
        split2(p2.x, p2.y, ah[kt][2], al[kt][2]);
        split2(p3.x, p3.y, ah[kt][3], al[kt][3]);
    }

    const bool odd = lane & 1;
    const int off = (tig & 2) ? 4 : 0;
    const int nr = odd ? n1 : n0;
    const bool vv = odd ? v1 : v0;

    asm volatile("cp.async.wait_group 0;");
    __syncthreads();

    #pragma unroll
    for (int p = 0; p < 16; ++p) {
        float c[4] = {0.f, 0.f, 0.f, 0.f};
        #pragma unroll
        for (int kt = 0; kt < 4; ++kt) {
            uint4 B = sB[(p * 4 + kt) * 32 + lane];
            mma_bf16(c, ah[kt], B.x, B.y);
            mma_bf16(c, ah[kt], B.z, B.w);
            mma_bf16(c, al[kt], B.x, B.y);
        }
        float r[4];
        frag_exchange(c, r, odd);

        const int cc = 8 * p + off;   // 0..127 within half
        float4 badd = make_float4(0.f, 0.f, 0.f, 0.f);
        float* table;
        int col;
        if (half == 0) {
            if (p < 8) {
                table = g_kx; col = cc;
                float4 a = *(const float4*)(bk + col);
                float4 b = *(const float4*)(bq + col);
                badd = make_float4(a.x + b.x, a.y + b.y, a.z + b.z, a.w + b.w);
            } else {
                table = g_qx; col = cc - 64;
            }
        } else {
            if (p < 8) {
                table = g_vx; col = cc;
                badd = *(const float4*)(bv + col);
            } else {
                table = out; col = cc - 64;
                badd = *(const float4*)(bias + col);
            }
        }
        if (vv) *(float4*)(table + (size_t)nr * 64 + col) =
            make_float4(r[0] + badd.x, r[1] + badd.y, r[2] + badd.z, r[3] + badd.w);
    }
}

// ----------------------------------------------------------------------------
// Edge kernel v11: frag-exchange drain, float4 gathers prefetched one block
// ahead, RED.v4 scatter.
// ----------------------------------------------------------------------------
#define TILE_E 128

__global__ __launch_bounds__(256, 2) void edge_kernel(
    const float* __restrict__ ea,
    const int* __restrict__ srcArr, const int* __restrict__ dstArr,
    float* __restrict__ out, int E)
{
    __shared__ uint4 sB[1024];   // 16KB

    const int tid  = threadIdx.x;
    const int w    = tid >> 5;
    const int lane = tid & 31;
    const int g    = lane >> 2;
    const int tig  = lane & 3;

    {
        unsigned sb = smem_u32(sB);
        #pragma unroll
        for (int i = 0; i < 4; ++i) {
            int idx = tid * 4 + i;
            asm volatile("cp.async.cg.shared.global [%0], [%1], 16;"
                         :: "r"(sb + idx * 16), "l"(g_Bpack + idx));
        }
        asm volatile("cp.async.commit_group;");
    }

    const long ebase = (long)blockIdx.x * TILE_E;
    long e0 = ebase + w * 16 + g;
    long e1 = e0 + 8;
    const bool v0 = (e0 < (long)E), v1 = (e1 < (long)E);
    const long e0c = v0 ? e0 : (long)E - 1;
    const long e1c = v1 ? e1 : (long)E - 1;

    uint32_t ah[2][4], al[2][4];
    #pragma unroll
    for (int kt = 0; kt < 2; ++kt) {
        const int k0 = kt * 16 + 2 * tig;
        float2 p0 = *(const float2*)(ea + e0c * 32 + k0);
        float2 p1 = *(const float2*)(ea + e1c * 32 + k0);
        float2 p2 = *(const float2*)(ea + e0c * 32 + k0 + 8);
        float2 p3 = *(const float2*)(ea + e1c * 32 + k0 + 8);
        split2(p0.x, p0.y, ah[kt][0], al[kt][0]);
        split2(p1.x, p1.y, ah[kt][1], al[kt][1]);
        split2(p2.x, p2.y, ah[kt][2], al[kt][2]);
        split2(p3.x, p3.y, ah[kt][3], al[kt][3]);
    }

    // Drain mapping is loop-invariant: even lanes own edge e0, odd own e1.
    const bool odd = lane & 1;
    const int off = (tig & 2) ? 4 : 0;
    const long ec = odd ? e1c : e0c;
    const bool vv = odd ? v1 : v0;
    const int dst = dstArr[ec], src = srcArr[ec];
    const float* kxr = g_kx + (size_t)dst * 64;
    const float* qxr = g_qx + (size_t)src * 64;
    const float* vxr = g_vx + (size_t)src * 64;
    float* outr = out + (size_t)dst * 64;

    asm volatile("cp.async.wait_group 0;");
    __syncthreads();

    // Prefetch gathers for block 0.
    float4 kdb = *(const float4*)(kxr + off);
    float4 qsb = *(const float4*)(qxr + off);
    float4 vsb = *(const float4*)(vxr + off);

    #pragma unroll
    for (int p = 0; p < 8; ++p) {
        float4 kd = kdb, qs = qsb, vs = vsb;
        if (p < 7) {
            const int cn = 8 * (p + 1) + off;
            kdb = *(const float4*)(kxr + cn);
            qsb = *(const float4*)(qxr + cn);
            vsb = *(const float4*)(vxr + cn);
        }
        float cg[4] = {0.f, 0.f, 0.f, 0.f};
        float cv[4] = {0.f, 0.f, 0.f, 0.f};
        #pragma unroll
        for (int kt = 0; kt < 2; ++kt) {
            uint4 Bg = sB[(p * 2 + kt) * 32 + lane];
            uint4 Bv = sB[((p + 8) * 2 + kt) * 32 + lane];
            mma_bf16(cg, ah[kt], Bg.x, Bg.y);
            mma_bf16(cg, ah[kt], Bg.z, Bg.w);
            mma_bf16(cg, al[kt], Bg.x, Bg.y);
            mma_bf16(cv, ah[kt], Bv.x, Bv.y);
            mma_bf16(cv, ah[kt], Bv.z, Bv.w);
            mma_bf16(cv, al[kt], Bv.x, Bv.y);
        }
        float rg[4], rv[4];
        frag_exchange(cg, rg, odd);
        frag_exchange(cv, rv, odd);

        const int c0 = 8 * p + off;
        float m0 = fast_sigmoid(rg[0] + kd.x + qs.x) * (rv[0] + vs.x);
        float m1 = fast_sigmoid(rg[1] + kd.y + qs.y) * (rv[1] + vs.y);
        float m2 = fast_sigmoid(rg[2] + kd.z + qs.z) * (rv[2] + vs.z);
        float m3 = fast_sigmoid(rg[3] + kd.w + qs.w) * (rv[3] + vs.w);
        if (vv)
            asm volatile("red.global.add.v4.f32 [%0], {%1,%2,%3,%4};"
                         :: "l"(outr + c0), "f"(m0), "f"(m1), "f"(m2), "f"(m3)
                         : "memory");
    }
}

// ----------------------------------------------------------------------------
// Launch. Inputs: x, edge_index, edge_attr, Wk, bk, Wq, bq, Wv, bv, Wskip, bias.
// ----------------------------------------------------------------------------
extern "C" void kernel_launch(void* const* d_in, const int* in_sizes, int n_in,
                              void* d_out, int out_size)
{
    const float* x     = (const float*)d_in[0];
    const int*   ei    = (const int*)d_in[1];
    const float* ea    = (const float*)d_in[2];
    const float* Wk    = (const float*)d_in[3];
    const float* bk    = (const float*)d_in[4];
    const float* Wq    = (const float*)d_in[5];
    const float* bq    = (const float*)d_in[6];
    const float* Wv    = (const float*)d_in[7];
    const float* bv    = (const float*)d_in[8];
    const float* Wskip = (const float*)d_in[9];
    const float* bias  = (const float*)d_in[10];
    float* out = (float*)d_out;

    int N = in_sizes[0] / 64;   // x is [N, 64]
    int E = in_sizes[2] / 32;   // edge_attr is [E, 32]

    bpack_kernel<<<3, 256>>>(Wk, Wq, Wv, Wskip);

    dim3 ngrid((N + 127) / 128, 2);
    node_kernel<<<ngrid, 256>>>(x, bk, bq, bv, bias, out, N);

    int numTiles = (E + TILE_E - 1) / TILE_E;
    edge_kernel<<<numTiles, 256>>>(ea, ei, ei + E, out, E);
}